// round 10
// baseline (speedup 1.0000x reference)
#include <cuda_runtime.h>
#include <cuda_bf16.h>

// ChannelPruner: out[b,o,h,w] = sum_c w[o,c] * x[b,c,h,w]
// x: (32, 256, 56, 56) fp32, w: (256, 256, 1, 1) fp32.
// Fused generic sparse-row kernel (correct for ANY w). 512-thread blocks,
// each handling TWO batch-planes of one output channel o:
//   - total threads unchanged vs best (2M) -> latency hiding preserved
//   - CTA count halved (8192 -> 4096)      -> less launch/prologue overhead
//   - per-thread MLP 4-6 independent loads -> better DRAM/L2 queue fill
// Plain stores (cache hints measured neutral-to-negative in R4/R5).
// (Resubmission of R8: previous bench failed on infra, kernel untested.)

#define N_CH   256
#define HW4    784          // 56*56/4 float4 per plane
#define NBATCH 32
#define TPB    512

__global__ __launch_bounds__(TPB, 4)
void channel_pruner_kernel(const float4* __restrict__ X,
                           const float4* __restrict__ W,   // row o = W[o*64 .. o*64+63]
                           float4* __restrict__ O)
{
    const int o   = blockIdx.x;           // output channel
    const int b0  = blockIdx.y * 2;       // first of two batches
    const int tid = threadIdx.x;          // 512 threads

    __shared__ int   s_cnt[64];
    __shared__ int   s_off[64];
    __shared__ int   s_nnz;
    __shared__ int   s_c[N_CH];
    __shared__ float s_v[N_CH];

    // --- Phase 1: cooperative scan of w row o (64 float4 = 256 floats) ---
    float4 w4;
    int myCnt = 0;
    if (tid < 64) {
        w4 = __ldg(&W[o * 64 + tid]);
        myCnt = (w4.x != 0.0f) + (w4.y != 0.0f) + (w4.z != 0.0f) + (w4.w != 0.0f);
        s_cnt[tid] = myCnt;
    }
    __syncthreads();

    if (tid == 0) {
        int run = 0;
        #pragma unroll
        for (int i = 0; i < 64; i++) { s_off[i] = run; run += s_cnt[i]; }
        s_nnz = run;
    }
    __syncthreads();

    if (tid < 64 && myCnt > 0) {
        int p = s_off[tid];
        const int cbase = tid * 4;
        if (w4.x != 0.0f) { s_c[p] = cbase + 0; s_v[p] = w4.x; p++; }
        if (w4.y != 0.0f) { s_c[p] = cbase + 1; s_v[p] = w4.y; p++; }
        if (w4.z != 0.0f) { s_c[p] = cbase + 2; s_v[p] = w4.z; p++; }
        if (w4.w != 0.0f) { s_c[p] = cbase + 3; s_v[p] = w4.w; p++; }
    }
    __syncthreads();

    const int nnz = s_nnz;
    const size_t planeStride = (size_t)N_CH * HW4;
    const float4* __restrict__ Xb0 = X + (size_t)b0 * planeStride;
    float4* __restrict__ Ob0 = O + (size_t)b0 * planeStride + (size_t)o * HW4;

    const int  s0   = tid;                 // always < 784
    const int  s1   = tid + TPB;           // valid iff tid < 784-512 = 272
    const bool has1 = (tid < HW4 - TPB);

    // --- Phase 2: stream two planes (batches b0, b0+1) ---
    if (nnz == 0) {
        const float4 z = make_float4(0.f, 0.f, 0.f, 0.f);
        Ob0[s0] = z;
        Ob0[planeStride + s0] = z;
        if (has1) {
            Ob0[s1] = z;
            Ob0[planeStride + s1] = z;
        }
    } else if (nnz == 1) {
        const float  v    = s_v[0];
        const size_t cOff = (size_t)s_c[0] * HW4;
        const float4* __restrict__ Xc0 = Xb0 + cOff;                // batch b0
        const float4* __restrict__ Xc1 = Xb0 + planeStride + cOff;  // batch b0+1
        // issue all independent loads first (MLP 4-6: two separate streams)
        float4 a00 = __ldg(&Xc0[s0]);
        float4 a10 = __ldg(&Xc1[s0]);
        float4 a01, a11;
        if (has1) {
            a01 = __ldg(&Xc0[s1]);
            a11 = __ldg(&Xc1[s1]);
        }
        a00.x *= v; a00.y *= v; a00.z *= v; a00.w *= v;
        a10.x *= v; a10.y *= v; a10.z *= v; a10.w *= v;
        Ob0[s0] = a00;
        Ob0[planeStride + s0] = a10;
        if (has1) {
            a01.x *= v; a01.y *= v; a01.z *= v; a01.w *= v;
            a11.x *= v; a11.y *= v; a11.z *= v; a11.w *= v;
            Ob0[s1] = a01;
            Ob0[planeStride + s1] = a11;
        }
    } else {
        // generic sparse accumulation (indices/values are smem hits)
        #pragma unroll
        for (int part = 0; part < 2; part++) {
            const int s = (part == 0) ? s0 : s1;
            if (part == 1 && !has1) break;
            float4 acc0 = make_float4(0.f, 0.f, 0.f, 0.f);
            float4 acc1 = acc0;
            for (int k = 0; k < nnz; k++) {
                const float  v   = s_v[k];
                const size_t off = (size_t)s_c[k] * HW4 + s;
                const float4 x0 = __ldg(&Xb0[off]);
                const float4 x1 = __ldg(&Xb0[planeStride + off]);
                acc0.x += v * x0.x; acc0.y += v * x0.y;
                acc0.z += v * x0.z; acc0.w += v * x0.w;
                acc1.x += v * x1.x; acc1.y += v * x1.y;
                acc1.z += v * x1.z; acc1.w += v * x1.w;
            }
            Ob0[s] = acc0;
            Ob0[planeStride + s] = acc1;
        }
    }
}

extern "C" void kernel_launch(void* const* d_in, const int* in_sizes, int n_in,
                              void* d_out, int out_size)
{
    const float4* X = (const float4*)d_in[0];   // x: 32*256*56*56 fp32
    const float4* W = (const float4*)d_in[1];   // conv_weights: 256*256*1*1 fp32
    float4* O = (float4*)d_out;

    dim3 grid(N_CH, NBATCH / 2);   // 4096 blocks: one per (o, 2-batch pair)
    channel_pruner_kernel<<<grid, TPB>>>(X, W, O);
}

// round 13
// speedup vs baseline: 1.0067x; 1.0067x over previous
#include <cuda_runtime.h>
#include <cuda_bf16.h>

// ChannelPruner: out[b,o,h,w] = sum_c w[o,c] * x[b,c,h,w]
// x: (32, 256, 56, 56) fp32, w: (256, 256, 1, 1) fp32.
// Fused generic sparse-row kernel (correct for ANY w), R1 launch shape
// (8192 blocks x 256 thr). L2 eviction-priority qualifiers on sm_103a
// require 256-bit accesses, so the hot path moves 32B units (.v4.b64):
//   x loads : ld.global.nc.L2::evict_last  (keep x resident in L2)
//   o stores: st.global.L2::evict_first    (write-once lines yield first)
// Plane = 784 float4 = 392 x 32B units; 392 = 256 + 136.

#define N_CH   256
#define HW4    784          // 56*56/4 float4 per plane
#define HW8    392          // 32-byte units per plane
#define NBATCH 32

struct f8 { float4 a, b; };

__device__ __forceinline__ f8 ldg_keep8(const void* p) {
    f8 r;
    asm("ld.global.nc.L2::evict_last.v4.b64 {%0,%1,%2,%3}, [%4];"
        : "=d"(*(double*)&r.a.x), "=d"(*(double*)&r.a.z),
          "=d"(*(double*)&r.b.x), "=d"(*(double*)&r.b.z)
        : "l"(p));
    return r;
}

__device__ __forceinline__ void stg_stream8(void* p, const f8& v) {
    asm volatile("st.global.L2::evict_first.v4.b64 [%0], {%1,%2,%3,%4};"
                 :: "l"(p),
                    "d"(*(const double*)&v.a.x), "d"(*(const double*)&v.a.z),
                    "d"(*(const double*)&v.b.x), "d"(*(const double*)&v.b.z)
                 : "memory");
}

__global__ __launch_bounds__(256, 8)
void channel_pruner_kernel(const float4* __restrict__ X,
                           const float4* __restrict__ W,   // row o = W[o*64 .. o*64+63]
                           float4* __restrict__ O)
{
    const int o   = blockIdx.x;    // output channel
    const int b   = blockIdx.y;    // batch
    const int tid = threadIdx.x;   // 256 threads

    __shared__ int   s_cnt[64];
    __shared__ int   s_off[64];
    __shared__ int   s_nnz;
    __shared__ int   s_c[N_CH];
    __shared__ float s_v[N_CH];

    // --- Phase 1: cooperative scan of w row o (64 float4 = 256 floats) ---
    float4 w4;
    int myCnt = 0;
    if (tid < 64) {
        w4 = __ldg(&W[o * 64 + tid]);
        myCnt = (w4.x != 0.0f) + (w4.y != 0.0f) + (w4.z != 0.0f) + (w4.w != 0.0f);
        s_cnt[tid] = myCnt;
    }
    __syncthreads();

    if (tid == 0) {
        int run = 0;
        #pragma unroll
        for (int i = 0; i < 64; i++) { s_off[i] = run; run += s_cnt[i]; }
        s_nnz = run;
    }
    __syncthreads();

    if (tid < 64 && myCnt > 0) {
        int p = s_off[tid];
        const int cbase = tid * 4;
        if (w4.x != 0.0f) { s_c[p] = cbase + 0; s_v[p] = w4.x; p++; }
        if (w4.y != 0.0f) { s_c[p] = cbase + 1; s_v[p] = w4.y; p++; }
        if (w4.z != 0.0f) { s_c[p] = cbase + 2; s_v[p] = w4.z; p++; }
        if (w4.w != 0.0f) { s_c[p] = cbase + 3; s_v[p] = w4.w; p++; }
    }
    __syncthreads();

    const int nnz = s_nnz;
    const size_t planeStride = (size_t)N_CH * HW4;   // in float4 units
    const char* __restrict__ XbB =
        (const char*)(X + (size_t)b * planeStride);
    char* __restrict__ ObB =
        (char*)(O + (size_t)b * planeStride + (size_t)o * HW4);

    const bool has1 = (tid < HW8 - 256);   // 392 = 256 + 136
    const size_t u0 = (size_t)tid * 32;
    const size_t u1 = (size_t)(tid + 256) * 32;

    // --- Phase 2: stream the plane in 32B units ---
    if (nnz == 0) {
        f8 z; z.a = make_float4(0.f,0.f,0.f,0.f); z.b = z.a;
        stg_stream8(ObB + u0, z);
        if (has1) stg_stream8(ObB + u1, z);
    } else if (nnz == 1) {
        const float v = s_v[0];
        const char* __restrict__ XcB = XbB + (size_t)s_c[0] * (HW4 * 16);
        f8 x0 = ldg_keep8(XcB + u0);
        f8 x1;
        if (has1) x1 = ldg_keep8(XcB + u1);
        x0.a.x *= v; x0.a.y *= v; x0.a.z *= v; x0.a.w *= v;
        x0.b.x *= v; x0.b.y *= v; x0.b.z *= v; x0.b.w *= v;
        stg_stream8(ObB + u0, x0);
        if (has1) {
            x1.a.x *= v; x1.a.y *= v; x1.a.z *= v; x1.a.w *= v;
            x1.b.x *= v; x1.b.y *= v; x1.b.z *= v; x1.b.w *= v;
            stg_stream8(ObB + u1, x1);
        }
    } else {
        // generic sparse accumulation over 32B units
        for (int u = tid; u < HW8; u += 256) {
            const size_t off = (size_t)u * 32;
            f8 acc;
            acc.a = make_float4(0.f,0.f,0.f,0.f);
            acc.b = acc.a;
            for (int k = 0; k < nnz; k++) {
                const float v = s_v[k];
                const f8 xv = ldg_keep8(XbB + (size_t)s_c[k] * (HW4 * 16) + off);
                acc.a.x += v * xv.a.x; acc.a.y += v * xv.a.y;
                acc.a.z += v * xv.a.z; acc.a.w += v * xv.a.w;
                acc.b.x += v * xv.b.x; acc.b.y += v * xv.b.y;
                acc.b.z += v * xv.b.z; acc.b.w += v * xv.b.w;
            }
            stg_stream8(ObB + off, acc);
        }
    }
}

extern "C" void kernel_launch(void* const* d_in, const int* in_sizes, int n_in,
                              void* d_out, int out_size)
{
    const float4* X = (const float4*)d_in[0];   // x: 32*256*56*56 fp32
    const float4* W = (const float4*)d_in[1];   // conv_weights: 256*256*1*1 fp32
    float4* O = (float4*)d_out;

    dim3 grid(N_CH, NBATCH);    // 8192 blocks: one per (b, o) plane
    channel_pruner_kernel<<<grid, 256>>>(X, W, O);
}